// round 11
// baseline (speedup 1.0000x reference)
#include <cuda_runtime.h>
#include <cuda_fp16.h>
#include <math.h>
#include <stdint.h>

#define LMAXX 10
#define NPTS  131072
#define WDIM  512

// ---------------- device scratch ----------------
__device__ float  g_KTAB[LMAXX+1][LMAXX+1];
__device__ float  g_DFACT[LMAXX+1];
__device__ __half g_act0[NPTS*WDIM];
__device__ __half g_act1[NPTS*WDIM];
__device__ float  g_h0[NPTS*8];
__device__ __half g_w1T[WDIM*WDIM];
__device__ __half g_w2T[WDIM*WDIM];
__device__ __half g_w3T[WDIM*WDIM];
__device__ __half g_wcT[32*WDIM];
__device__ float  g_bcPad[32];

__constant__ float LAMBERT_C[11] = {
    3.1415926535897927f, 2.0943951023931957f, 0.7853981633974483f, 0.0f,
    -0.13089969389957473f, 0.0f, 0.04908738521234052f, 0.0f,
    -0.024543692606170262f, 0.0f, 0.014317154020265985f};

// ---------------- common helpers ----------------
__device__ __forceinline__ uint32_t smem_u32(const void* p) {
    uint32_t a;
    asm("{ .reg .u64 t; cvta.to.shared.u64 t, %1; cvt.u32.u64 %0, t; }" : "=r"(a) : "l"(p));
    return a;
}
__device__ __forceinline__ void cp16(uint32_t smem, const void* g) {
    asm volatile("cp.async.ca.shared.global [%0], [%1], 16;\n" :: "r"(smem), "l"(g));
}
__device__ __forceinline__ void cp_commit() { asm volatile("cp.async.commit_group;\n"); }
__device__ __forceinline__ void cp_wait1()  { asm volatile("cp.async.wait_group 1;\n"); }
__device__ __forceinline__ void cp_wait0()  { asm volatile("cp.async.wait_group 0;\n"); }
#define SW128(o) ((o) ^ (((o) >> 3) & 0x70))

__device__ __forceinline__ void mma16816(float* d, const uint32_t* a, const uint32_t* b) {
    asm volatile(
        "mma.sync.aligned.m16n8k16.row.col.f32.f16.f16.f32 "
        "{%0,%1,%2,%3}, {%4,%5,%6,%7}, {%8,%9}, {%0,%1,%2,%3};\n"
        : "+f"(d[0]), "+f"(d[1]), "+f"(d[2]), "+f"(d[3])
        : "r"(a[0]), "r"(a[1]), "r"(a[2]), "r"(a[3]), "r"(b[0]), "r"(b[1]));
}
#define LDSM_X4(r, addr) \
    asm volatile("ldmatrix.sync.aligned.m8n8.x4.shared.b16 {%0,%1,%2,%3}, [%4];" \
        : "=r"((r)[0]), "=r"((r)[1]), "=r"((r)[2]), "=r"((r)[3]) : "r"(addr))

// ---------------- big GEMM: C[M][512] = relu(A[M][512] @ BT^T + bias) ----------------
// Tile: BM=128 x BN=64, 256 threads (8 warps: 4 over M, 2 over N; 32x32 per warp).
// 2-stage cp.async ring, BK=64 (128B SW128 rows). smem = 50KB -> 2-3 CTAs/SM.
#define S_ABUF   16384           // 128 rows x 128B
#define S_BBUF   8192            // 64 rows x 128B
#define S_OFFBI  0
#define S_OFFA   1024
#define S_OFFB   (S_OFFA + 2*S_ABUF)      // 33792
#define S_SMEM   (S_OFFB + 2*S_BBUF)      // 50176

__device__ __forceinline__ void g_load_stage(uint32_t sb, const __half* A, const __half* BT,
                                             long rowbase, int nbase, int tid, int buf, int k0) {
#pragma unroll
    for (int i = 0; i < 4; i++) {          // A: 1024 16B chunks
        int t = tid + i * 256;
        int r = t >> 3, c = t & 7;
        uint32_t off = (uint32_t)(r * 128 + c * 16);
        cp16(sb + S_OFFA + buf * S_ABUF + SW128(off), &A[(rowbase + r) * WDIM + k0 + c * 8]);
    }
#pragma unroll
    for (int i = 0; i < 2; i++) {          // B: 512 16B chunks
        int t = tid + i * 256;
        int r = t >> 3, c = t & 7;
        uint32_t off = (uint32_t)(r * 128 + c * 16);
        cp16(sb + S_OFFB + buf * S_BBUF + SW128(off), &BT[(long)(nbase + r) * WDIM + k0 + c * 8]);
    }
    cp_commit();
}

__global__ void __launch_bounds__(256, 3)
gemm_uni_kernel(const __half* __restrict__ A, const __half* __restrict__ BT,
                const float* __restrict__ bias, __half* __restrict__ C, int M) {
    extern __shared__ __align__(1024) char smem[];
    uint32_t sb = smem_u32(smem);
    int tid = threadIdx.x, wid = tid >> 5, lid = tid & 31;
    long rowbase = (long)blockIdx.y * 128;
    int nbase = blockIdx.x * 64;
    float* biasS = (float*)(smem + S_OFFBI);
    if (tid < 64) biasS[tid] = bias[nbase + tid];

    int wm = wid & 3, wn = wid >> 2;       // 4 x 2 warp grid: 32 rows x 32 cols per warp
    int g = lid >> 2, t4 = lid & 3;
    int part = lid >> 3, r8 = lid & 7;
    int prow = (part & 1) * 8 + r8;        // row within 16-row ldmatrix group
    int pkb  = (part >> 1) * 16;           // byte offset selecting k8 half

    float acc[2][4][4];
#pragma unroll
    for (int a_ = 0; a_ < 2; a_++)
#pragma unroll
        for (int b_ = 0; b_ < 4; b_++)
#pragma unroll
            for (int c_ = 0; c_ < 4; c_++) acc[a_][b_][c_] = 0.0f;

    constexpr int NS = WDIM / 64;  // 8
    g_load_stage(sb, A, BT, rowbase, nbase, tid, 0, 0);
    for (int s = 0; s < NS; s++) {
        int buf = s & 1;
        if (s + 1 < NS) { g_load_stage(sb, A, BT, rowbase, nbase, tid, buf ^ 1, (s + 1) * 64); cp_wait1(); }
        else cp_wait0();
        __syncthreads();

        uint32_t sbA = sb + S_OFFA + buf * S_ABUF;
        uint32_t sbB = sb + S_OFFB + buf * S_BBUF;
#pragma unroll
        for (int kk = 0; kk < 64; kk += 16) {
            uint32_t a[2][4], b[2][4];
#pragma unroll
            for (int sm_ = 0; sm_ < 2; sm_++) {
                int row = wm * 32 + sm_ * 16 + prow;
                LDSM_X4(a[sm_], sbA + SW128((uint32_t)(row * 128 + kk * 2 + pkb)));
            }
#pragma unroll
            for (int j2 = 0; j2 < 2; j2++) {
                int row = wn * 32 + j2 * 16 + prow;
                LDSM_X4(b[j2], sbB + SW128((uint32_t)(row * 128 + kk * 2 + pkb)));
            }
#pragma unroll
            for (int sm_ = 0; sm_ < 2; sm_++) {
#pragma unroll
                for (int j2 = 0; j2 < 2; j2++) {
                    uint32_t blo[2] = {b[j2][0], b[j2][2]};
                    uint32_t bhi[2] = {b[j2][1], b[j2][3]};
                    mma16816(acc[sm_][2 * j2],     a[sm_], blo);
                    mma16816(acc[sm_][2 * j2 + 1], a[sm_], bhi);
                }
            }
        }
        __syncthreads();
    }

#pragma unroll
    for (int sm_ = 0; sm_ < 2; sm_++) {
#pragma unroll
        for (int j = 0; j < 4; j++) {
            long r0 = rowbase + wm * 32 + sm_ * 16 + g;
            int cl = wn * 32 + j * 8 + t4 * 2;
            int c0 = nbase + cl;
            float bx = biasS[cl], by = biasS[cl + 1];
            float v0 = fmaxf(acc[sm_][j][0] + bx, 0.f);
            float v1 = fmaxf(acc[sm_][j][1] + by, 0.f);
            float v2 = fmaxf(acc[sm_][j][2] + bx, 0.f);
            float v3 = fmaxf(acc[sm_][j][3] + by, 0.f);
            *(__half2*)&C[r0 * WDIM + c0]       = __floats2half2_rn(v0, v1);
            *(__half2*)&C[(r0 + 8) * WDIM + c0] = __floats2half2_rn(v2, v3);
        }
    }
}

__device__ __forceinline__ float sigmoidf_(float x) { return 1.0f / (1.0f + expf(-x)); }

// ---------------- wc GEMM (N=32) fused with final epilogue ----------------
__global__ void __launch_bounds__(128) wc_final_kernel(
    const __half* __restrict__ A, const __half* __restrict__ BT,
    const float* __restrict__ bias, const float* __restrict__ feature,
    float* __restrict__ out, int N) {
    constexpr int BM = 128, BK = 32, BN = 32, NTH = 128;
    constexpr int LDA = BK + 8;
    __shared__ __half As[2][BM][LDA];
    __shared__ __half Bs[2][BN][LDA];
    __shared__ float cs_s[128][28];
    int tid = threadIdx.x;
    int warp = tid >> 5, lane = tid & 31;
    int wm = warp;
    int g = lane >> 2, t4 = lane & 3;
    long rowbase = (long)blockIdx.y * BM;

    float acc[2][4][4];
#pragma unroll
    for (int a_ = 0; a_ < 2; a_++)
#pragma unroll
        for (int b_ = 0; b_ < 4; b_++)
#pragma unroll
            for (int c_ = 0; c_ < 4; c_++) acc[a_][b_][c_] = 0.0f;

    auto load_stage = [&](int buf, int k0) {
#pragma unroll
        for (int t = tid; t < BM * (BK/8); t += NTH) {
            int r = t >> 2, seg = t & 3;
            cp16(smem_u32(&As[buf][r][seg*8]), &A[(rowbase + r) * WDIM + k0 + seg*8]);
        }
#pragma unroll
        for (int t = tid; t < BN * (BK/8); t += NTH) {
            int r = t >> 2, seg = t & 3;
            cp16(smem_u32(&Bs[buf][r][seg*8]), &BT[(long)r * WDIM + k0 + seg*8]);
        }
        cp_commit();
    };

    constexpr int NS = WDIM / BK;
    load_stage(0, 0);
    for (int s = 0; s < NS; s++) {
        int cur = s & 1;
        if (s + 1 < NS) { load_stage(cur ^ 1, (s + 1) * BK); cp_wait1(); }
        else cp_wait0();
        __syncthreads();
#pragma unroll
        for (int kk = 0; kk < BK; kk += 16) {
            uint32_t a[2][4], b[4][2];
#pragma unroll
            for (int sm_ = 0; sm_ < 2; sm_++) {
                int r = wm*32 + sm_*16;
                a[sm_][0] = *(const uint32_t*)&As[cur][r + g    ][kk + t4*2    ];
                a[sm_][1] = *(const uint32_t*)&As[cur][r + g + 8][kk + t4*2    ];
                a[sm_][2] = *(const uint32_t*)&As[cur][r + g    ][kk + t4*2 + 8];
                a[sm_][3] = *(const uint32_t*)&As[cur][r + g + 8][kk + t4*2 + 8];
            }
#pragma unroll
            for (int j = 0; j < 4; j++) {
                int n = j*8;
                b[j][0] = *(const uint32_t*)&Bs[cur][n + g][kk + t4*2    ];
                b[j][1] = *(const uint32_t*)&Bs[cur][n + g][kk + t4*2 + 8];
            }
#pragma unroll
            for (int sm_ = 0; sm_ < 2; sm_++)
#pragma unroll
                for (int j = 0; j < 4; j++)
                    mma16816(acc[sm_][j], a[sm_], b[j]);
        }
        __syncthreads();
    }

#pragma unroll
    for (int sm_ = 0; sm_ < 2; sm_++) {
#pragma unroll
        for (int j = 0; j < 4; j++) {
            int r0 = wm*32 + sm_*16 + g;
            int c0 = j*8 + t4*2;
            if (c0 < 27) {
                cs_s[r0][c0]     = acc[sm_][j][0] + bias[c0];
                cs_s[r0 + 8][c0] = acc[sm_][j][2] + bias[c0];
            }
            if (c0 + 1 < 27) {
                cs_s[r0][c0 + 1]     = acc[sm_][j][1] + bias[c0 + 1];
                cs_s[r0 + 8][c0 + 1] = acc[sm_][j][3] + bias[c0 + 1];
            }
        }
    }
    __syncthreads();

    long i = rowbase + tid;
    float coe[9];
#pragma unroll
    for (int k = 0; k < 9; k++) coe[k] = feature[i*16 + 1 + k];
    float rr = 0.f, gg = 0.f, bb = 0.f;
#pragma unroll
    for (int k = 0; k < 9; k++) {
        rr += cs_s[tid][k]      * coe[k];
        gg += cs_s[tid][9 + k]  * coe[k];
        bb += cs_s[tid][18 + k] * coe[k];
    }
    float gate[3] = {sigmoidf_(rr), sigmoidf_(gg), sigmoidf_(bb)};
#pragma unroll
    for (int cc = 0; cc < 3; cc++) {
        float spec = sigmoidf_(feature[i*16 + 13 + cc]);
        float light = out[(size_t)12*N + 3*i + cc];
        float specular = spec * light * gate[cc];
        out[(size_t)9*N + 3*i + cc] = specular;
        out[3*i + cc] = out[(size_t)6*N + 3*i + cc] + specular;
    }
}

// ---------------- weight prep (+ consts, merged) ----------------
__global__ void prep_weights_kernel(const float* __restrict__ w1, const float* __restrict__ w2,
                                    const float* __restrict__ w3, const float* __restrict__ wc,
                                    const float* __restrict__ bc) {
    int idx = blockIdx.x * blockDim.x + threadIdx.x;
    if (idx == 0) {
        double fact[22];
        fact[0] = 1.0;
        for (int i = 1; i <= 21; i++) fact[i] = fact[i-1] * i;
        for (int l = 0; l <= LMAXX; l++)
            for (int m = 0; m <= l; m++) {
                double K = sqrt((2.0*l + 1.0) / (4.0*M_PI) * fact[l-m] / fact[l+m]);
                g_KTAB[l][m] = (float)(m == 0 ? K : sqrt(2.0) * K);
            }
        double df = 1.0;
        g_DFACT[0] = 1.0f;
        for (int m = 1; m <= LMAXX; m++) { df *= (2.0*m - 1.0); g_DFACT[m] = (float)df; }
    }
    const int NW = 3 * WDIM * WDIM;
    if (idx < NW) {
        int which = idx >> 18;
        int r = idx & (WDIM*WDIM - 1);
        int k = r >> 9, n = r & 511;
        const float* w = (which == 0) ? w1 : (which == 1) ? w2 : w3;
        __half* o = (which == 0) ? g_w1T : (which == 1) ? g_w2T : g_w3T;
        o[n*WDIM + k] = __float2half(w[k*WDIM + n]);
    } else if (idx < NW + 32*WDIM) {
        int r = idx - NW;
        int k = r & 511, n = r >> 9;
        g_wcT[n*WDIM + k] = __float2half(n < 27 ? wc[k*27 + n] : 0.0f);
    } else if (idx < NW + 32*WDIM + 32) {
        int n = idx - (NW + 32*WDIM);
        g_bcPad[n] = n < 27 ? bc[n] : 0.0f;
    }
}

// ---------------- physics: fused dual SH accumulation, unit directions ----------------
__global__ void physics_kernel(const float* __restrict__ normals,
                               const float* __restrict__ viewd,
                               const float* __restrict__ feature,
                               const float* __restrict__ refSH,
                               float* __restrict__ out, int N) {
    __shared__ float ss[32 * 363];
    int lane = threadIdx.x;
    int base = blockIdx.x * 32;
    int i = base + lane;

    const float4* src = (const float4*)(refSH + (size_t)base * 363);
    float4* dst = (float4*)ss;
    for (int t = lane; t < (32*363)/4; t += 32) dst[t] = src[t];
    __syncwarp();

    float nx = normals[i*3+0], ny = normals[i*3+1], nz = normals[i*3+2];
    float vx = viewd[i*3+0],   vy = viewd[i*3+1],   vz = viewd[i*3+2];
    float f0 = feature[i*16];
    float rough = fmaxf(f0, 0.0f) + log1pf(expf(-fabsf(f0)));
    float dotnv = nx*vx + ny*vy + nz*vz;
    float wx = 2.0f*nx*dotnv - vx;
    float wy = 2.0f*ny*dotnv - vy;
    float wz = 2.0f*nz*dotnv - vz;

    const float* row = ss + lane * 363;

    float cA[LMAXX+1], sA[LMAXX+1], cB[LMAXX+1], sB[LMAXX+1];
    cA[0] = 1.0f; sA[0] = 0.0f; cB[0] = 1.0f; sB[0] = 0.0f;
#pragma unroll
    for (int m = 1; m <= LMAXX; m++) {
        cA[m] = nx*cA[m-1] - ny*sA[m-1];
        sA[m] = nx*sA[m-1] + ny*cA[m-1];
        cB[m] = wx*cB[m-1] - wy*sB[m-1];
        sB[m] = wx*sB[m-1] + wy*cB[m-1];
    }
    float wlB[LMAXX+1];
#pragma unroll
    for (int l = 0; l <= LMAXX; l++) wlB[l] = expf(-(float)(l*(l+1)) * 0.5f * rough);

    float aI[3] = {0.f,0.f,0.f}, aL[3] = {0.f,0.f,0.f};

#pragma unroll
    for (int m = 0; m <= LMAXX; m++) {
        float QAa = g_DFACT[m], QBa = QAa;
        {
            float kw = g_KTAB[m][m];
            float fA = kw * QAa * LAMBERT_C[m];
            float fB = kw * QBa * wlB[m];
            int b = (m*m + m) * 3;
            if (m == 0) {
#pragma unroll
                for (int cc = 0; cc < 3; cc++) {
                    float rv = row[b+cc];
                    aI[cc] += fA*rv; aL[cc] += fB*rv;
                }
            } else {
                float pA = fA*cA[m], qA = fA*sA[m];
                float pB = fB*cB[m], qB = fB*sB[m];
#pragma unroll
                for (int cc = 0; cc < 3; cc++) {
                    float rp_ = row[b+3*m+cc], rm_ = row[b-3*m+cc];
                    aI[cc] += pA*rp_ + qA*rm_;
                    aL[cc] += pB*rp_ + qB*rm_;
                }
            }
        }
        if (m < LMAXX) {
            float QAb = (2.0f*m + 1.0f) * nz * QAa;
            float QBb = (2.0f*m + 1.0f) * wz * QBa;
            {
                int l = m + 1;
                float kw = g_KTAB[l][m];
                float fA = kw * QAb * LAMBERT_C[l];
                float fB = kw * QBb * wlB[l];
                int b = (l*l + l) * 3;
                if (m == 0) {
#pragma unroll
                    for (int cc = 0; cc < 3; cc++) {
                        float rv = row[b+cc];
                        aI[cc] += fA*rv; aL[cc] += fB*rv;
                    }
                } else {
                    float pA = fA*cA[m], qA = fA*sA[m];
                    float pB = fB*cB[m], qB = fB*sB[m];
#pragma unroll
                    for (int cc = 0; cc < 3; cc++) {
                        float rp_ = row[b+3*m+cc], rm_ = row[b-3*m+cc];
                        aI[cc] += pA*rp_ + qA*rm_;
                        aL[cc] += pB*rp_ + qB*rm_;
                    }
                }
            }
#pragma unroll
            for (int l = m + 2; l <= LMAXX; l++) {
                float inv_lm = 1.0f / (float)(l - m);
                float c1 = (2.0f*l - 1.0f), c2 = (float)(l + m - 1);
                float QAc = (c1 * nz * QAb - c2 * QAa) * inv_lm;
                float QBc = (c1 * wz * QBb - c2 * QBa) * inv_lm;
                QAa = QAb; QAb = QAc;
                QBa = QBb; QBb = QBc;
                float kw = g_KTAB[l][m];
                float fA = kw * QAc * LAMBERT_C[l];
                float fB = kw * QBc * wlB[l];
                int b = (l*l + l) * 3;
                if (m == 0) {
#pragma unroll
                    for (int cc = 0; cc < 3; cc++) {
                        float rv = row[b+cc];
                        aI[cc] += fA*rv; aL[cc] += fB*rv;
                    }
                } else {
                    float pA = fA*cA[m], qA = fA*sA[m];
                    float pB = fB*cB[m], qB = fB*sB[m];
#pragma unroll
                    for (int cc = 0; cc < 3; cc++) {
                        float rp_ = row[b+3*m+cc], rm_ = row[b-3*m+cc];
                        aI[cc] += pA*rp_ + qA*rm_;
                        aL[cc] += pB*rp_ + qB*rm_;
                    }
                }
            }
        }
    }

#pragma unroll
    for (int cc = 0; cc < 3; cc++) {
        float ir = fmaxf(aI[cc], 0.0f);
        float li = fmaxf(aL[cc], 0.0f);
        float alb = sigmoidf_(feature[i*16 + 10 + cc]);
        out[(size_t)3*N  + 3*i + cc] = alb;
        out[(size_t)6*N  + 3*i + cc] = alb * ir;
        out[(size_t)12*N + 3*i + cc] = li;
        out[(size_t)15*N + 3*i + cc] = ir;
    }
    float* h = g_h0 + (size_t)i * 8;
    h[0] = dotnv; h[1] = vx; h[2] = vy; h[3] = vz;
    h[4] = nx; h[5] = ny; h[6] = nz; h[7] = rough;
}

// ---------------- layer0 v3 ----------------
__global__ void __launch_bounds__(256) layer0_kernel_v3(
    const float* __restrict__ w0, const float* __restrict__ b0, int N) {
    __shared__ float sw[8 * WDIM];
    __shared__ float sbias[WDIM];
    __shared__ float sh[64 * 8];
    int tid = threadIdx.x;
    long base = (long)blockIdx.x * 64;

    for (int i = tid; i < 8 * WDIM; i += 256) sw[i] = w0[i];
    for (int i = tid; i < WDIM; i += 256) sbias[i] = b0[i];
    for (int i = tid; i < 64 * 8 / 4; i += 256)
        ((float4*)sh)[i] = ((const float4*)(g_h0 + base * 8))[i];
    __syncthreads();

    int c0 = (tid & 127) * 4;
    int rg = tid >> 7;

    float w[8][4], bb[4];
#pragma unroll
    for (int j = 0; j < 8; j++)
#pragma unroll
        for (int i = 0; i < 4; i++) w[j][i] = sw[j * WDIM + c0 + i];
#pragma unroll
    for (int i = 0; i < 4; i++) bb[i] = sbias[c0 + i];

    for (int r = rg; r < 64; r += 2) {
        const float* hh = sh + r * 8;
        __half res[4];
#pragma unroll
        for (int i = 0; i < 4; i++) {
            float acc = bb[i];
#pragma unroll
            for (int j = 0; j < 8; j++) acc += hh[j] * w[j][i];
            res[i] = __float2half(fmaxf(acc, 0.0f));
        }
        *(uint2*)&g_act0[(base + r) * WDIM + c0] = *(uint2*)res;
    }
}

// ---------------- launch ----------------
extern "C" void kernel_launch(void* const* d_in, const int* in_sizes, int n_in,
                              void* d_out, int out_size) {
    const float* normals = (const float*)d_in[0];
    const float* viewd   = (const float*)d_in[1];
    const float* feature = (const float*)d_in[2];
    const float* refSH   = (const float*)d_in[3];
    const float* w0 = (const float*)d_in[4];
    const float* b0 = (const float*)d_in[5];
    const float* b1 = (const float*)d_in[7];
    const float* b2 = (const float*)d_in[9];
    const float* b3 = (const float*)d_in[11];
    int N = in_sizes[0] / 3;
    float* out = (float*)d_out;

    __half *act0, *act1, *w1T, *w2T, *w3T, *wcT;
    float *bcPad;
    cudaGetSymbolAddress((void**)&act0, g_act0);
    cudaGetSymbolAddress((void**)&act1, g_act1);
    cudaGetSymbolAddress((void**)&w1T, g_w1T);
    cudaGetSymbolAddress((void**)&w2T, g_w2T);
    cudaGetSymbolAddress((void**)&w3T, g_w3T);
    cudaGetSymbolAddress((void**)&wcT, g_wcT);
    cudaGetSymbolAddress((void**)&bcPad, g_bcPad);

    cudaFuncSetAttribute(gemm_uni_kernel, cudaFuncAttributeMaxDynamicSharedMemorySize, S_SMEM);
    cudaFuncSetAttribute(gemm_uni_kernel, cudaFuncAttributePreferredSharedMemoryCarveout,
                         cudaSharedmemCarveoutMaxShared);

    int prepTotal = 3*WDIM*WDIM + 32*WDIM + 32;
    prep_weights_kernel<<<(prepTotal + 255)/256, 256>>>((const float*)d_in[6], (const float*)d_in[8],
                                                        (const float*)d_in[10], (const float*)d_in[12],
                                                        (const float*)d_in[13]);

    physics_kernel<<<N/32, 32>>>(normals, viewd, feature, refSH, out, N);

    layer0_kernel_v3<<<N/64, 256>>>(w0, b0, N);

    dim3 gg(WDIM/64, N/128);   // 8 x 1024
    gemm_uni_kernel<<<gg, 256, S_SMEM>>>(act0, w1T, b1, act1, N);
    gemm_uni_kernel<<<gg, 256, S_SMEM>>>(act1, w2T, b2, act0, N);
    gemm_uni_kernel<<<gg, 256, S_SMEM>>>(act0, w3T, b3, act1, N);

    wc_final_kernel<<<dim3(1, N/128), 128>>>(act1, wcT, bcPad, feature, out, N);
}

// round 16
// speedup vs baseline: 1.0840x; 1.0840x over previous
#include <cuda_runtime.h>
#include <cuda_fp16.h>
#include <math.h>
#include <stdint.h>

#define LMAXX 10
#define NPTS  131072
#define WDIM  512

// ---------------- device scratch ----------------
__device__ float  g_KTAB[LMAXX+1][LMAXX+1];
__device__ float  g_DFACT[LMAXX+1];
__device__ __half g_act0[NPTS*WDIM];
__device__ __half g_act1[NPTS*WDIM];
__device__ float  g_h0[NPTS*8];
__device__ __half g_w1T[WDIM*WDIM];
__device__ __half g_w2T[WDIM*WDIM];
__device__ __half g_w3T[WDIM*WDIM];
__device__ __half g_wcT[32*WDIM];
__device__ float  g_bcPad[32];

__constant__ float LAMBERT_C[11] = {
    3.1415926535897927f, 2.0943951023931957f, 0.7853981633974483f, 0.0f,
    -0.13089969389957473f, 0.0f, 0.04908738521234052f, 0.0f,
    -0.024543692606170262f, 0.0f, 0.014317154020265985f};

// ---------------- common helpers ----------------
__device__ __forceinline__ uint32_t smem_u32(const void* p) {
    uint32_t a;
    asm("{ .reg .u64 t; cvta.to.shared.u64 t, %1; cvt.u32.u64 %0, t; }" : "=r"(a) : "l"(p));
    return a;
}
__device__ __forceinline__ void cp16(uint32_t smem, const void* g) {
    asm volatile("cp.async.ca.shared.global [%0], [%1], 16;\n" :: "r"(smem), "l"(g));
}
__device__ __forceinline__ void cp_commit() { asm volatile("cp.async.commit_group;\n"); }
__device__ __forceinline__ void cp_wait1()  { asm volatile("cp.async.wait_group 1;\n"); }
__device__ __forceinline__ void cp_wait0()  { asm volatile("cp.async.wait_group 0;\n"); }
#define SW128(o) ((o) ^ (((o) >> 3) & 0x70))

__device__ __forceinline__ void mma16816(float* d, const uint32_t* a, const uint32_t* b) {
    asm volatile(
        "mma.sync.aligned.m16n8k16.row.col.f32.f16.f16.f32 "
        "{%0,%1,%2,%3}, {%4,%5,%6,%7}, {%8,%9}, {%0,%1,%2,%3};\n"
        : "+f"(d[0]), "+f"(d[1]), "+f"(d[2]), "+f"(d[3])
        : "r"(a[0]), "r"(a[1]), "r"(a[2]), "r"(a[3]), "r"(b[0]), "r"(b[1]));
}
#define LDSM_X4(r, addr) \
    asm volatile("ldmatrix.sync.aligned.m8n8.x4.shared.b16 {%0,%1,%2,%3}, [%4];" \
        : "=r"((r)[0]), "=r"((r)[1]), "=r"((r)[2]), "=r"((r)[3]) : "r"(addr))

// ---------------- big GEMM: BM=128 x BN=128 x BK=64, 2-stage, 66.5KB -> 2 CTAs/SM ----------------
#define G_ABUF   16384           // 128 rows x 128B per stage
#define G_OFFBI  0
#define G_OFFA   1024
#define G_OFFB   (G_OFFA + 2*G_ABUF)      // 33792
#define G_SMEM   (G_OFFB + 2*G_ABUF)      // 66560

__device__ __forceinline__ void g_load_stage(uint32_t sb, const __half* A, const __half* BT,
                                             long rowbase, int nbase, int tid, int buf, int k0) {
#pragma unroll
    for (int i = 0; i < 4; i++) {
        int t = tid + i * 256;
        int r = t >> 3, c = t & 7;
        uint32_t off = (uint32_t)(r * 128 + c * 16);
        cp16(sb + G_OFFA + buf * G_ABUF + SW128(off), &A[(rowbase + r) * WDIM + k0 + c * 8]);
    }
#pragma unroll
    for (int i = 0; i < 4; i++) {
        int t = tid + i * 256;
        int r = t >> 3, c = t & 7;
        uint32_t off = (uint32_t)(r * 128 + c * 16);
        cp16(sb + G_OFFB + buf * G_ABUF + SW128(off), &BT[(long)(nbase + r) * WDIM + k0 + c * 8]);
    }
    cp_commit();
}

__global__ void __launch_bounds__(256, 2)
gemm_uni_kernel(const __half* __restrict__ A, const __half* __restrict__ BT,
                const float* __restrict__ bias, __half* __restrict__ C, int M) {
    extern __shared__ __align__(1024) char smem[];
    uint32_t sb = smem_u32(smem);
    int tid = threadIdx.x, wid = tid >> 5, lid = tid & 31;
    long rowbase = (long)blockIdx.y * 128;
    int nbase = blockIdx.x * 128;
    float* biasS = (float*)(smem + G_OFFBI);
    for (int i = tid; i < 128; i += 256) biasS[i] = bias[nbase + i];

    int wm = wid & 3, wn = wid >> 2;       // 4 x 2: warp tile 32 rows x 64 cols
    int g = lid >> 2, t4 = lid & 3;
    int part = lid >> 3, r8 = lid & 7;
    int prow = (part & 1) * 8 + r8;
    int pkb  = (part >> 1) * 16;

    float acc[2][8][4];
#pragma unroll
    for (int a_ = 0; a_ < 2; a_++)
#pragma unroll
        for (int b_ = 0; b_ < 8; b_++)
#pragma unroll
            for (int c_ = 0; c_ < 4; c_++) acc[a_][b_][c_] = 0.0f;

    constexpr int NS = WDIM / 64;  // 8
    g_load_stage(sb, A, BT, rowbase, nbase, tid, 0, 0);
    for (int s = 0; s < NS; s++) {
        int buf = s & 1;
        if (s + 1 < NS) { g_load_stage(sb, A, BT, rowbase, nbase, tid, buf ^ 1, (s + 1) * 64); cp_wait1(); }
        else cp_wait0();
        __syncthreads();

        uint32_t sbA = sb + G_OFFA + buf * G_ABUF;
        uint32_t sbB = sb + G_OFFB + buf * G_ABUF;
#pragma unroll
        for (int kk = 0; kk < 64; kk += 16) {
            uint32_t a[2][4], b[4][4];
#pragma unroll
            for (int sm_ = 0; sm_ < 2; sm_++) {
                int row = wm * 32 + sm_ * 16 + prow;
                LDSM_X4(a[sm_], sbA + SW128((uint32_t)(row * 128 + kk * 2 + pkb)));
            }
#pragma unroll
            for (int j2 = 0; j2 < 4; j2++) {
                int row = wn * 64 + j2 * 16 + prow;
                LDSM_X4(b[j2], sbB + SW128((uint32_t)(row * 128 + kk * 2 + pkb)));
            }
#pragma unroll
            for (int sm_ = 0; sm_ < 2; sm_++) {
#pragma unroll
                for (int j2 = 0; j2 < 4; j2++) {
                    uint32_t blo[2] = {b[j2][0], b[j2][2]};
                    uint32_t bhi[2] = {b[j2][1], b[j2][3]};
                    mma16816(acc[sm_][2 * j2],     a[sm_], blo);
                    mma16816(acc[sm_][2 * j2 + 1], a[sm_], bhi);
                }
            }
        }
        __syncthreads();
    }

#pragma unroll
    for (int sm_ = 0; sm_ < 2; sm_++) {
#pragma unroll
        for (int j = 0; j < 8; j++) {
            long r0 = rowbase + wm * 32 + sm_ * 16 + g;
            int cl = wn * 64 + j * 8 + t4 * 2;
            int c0 = nbase + cl;
            float bx = biasS[cl], by = biasS[cl + 1];
            float v0 = fmaxf(acc[sm_][j][0] + bx, 0.f);
            float v1 = fmaxf(acc[sm_][j][1] + by, 0.f);
            float v2 = fmaxf(acc[sm_][j][2] + bx, 0.f);
            float v3 = fmaxf(acc[sm_][j][3] + by, 0.f);
            *(__half2*)&C[r0 * WDIM + c0]       = __floats2half2_rn(v0, v1);
            *(__half2*)&C[(r0 + 8) * WDIM + c0] = __floats2half2_rn(v2, v3);
        }
    }
}

__device__ __forceinline__ float sigmoidf_(float x) { return 1.0f / (1.0f + expf(-x)); }

// ---------------- wc GEMM (N=32) fused with final epilogue ----------------
__global__ void __launch_bounds__(128) wc_final_kernel(
    const __half* __restrict__ A, const __half* __restrict__ BT,
    const float* __restrict__ bias, const float* __restrict__ feature,
    float* __restrict__ out, int N) {
    constexpr int BM = 128, BK = 32, BN = 32, NTH = 128;
    constexpr int LDA = BK + 8;
    __shared__ __half As[2][BM][LDA];
    __shared__ __half Bs[2][BN][LDA];
    __shared__ float cs_s[128][28];
    int tid = threadIdx.x;
    int warp = tid >> 5, lane = tid & 31;
    int wm = warp;
    int g = lane >> 2, t4 = lane & 3;
    long rowbase = (long)blockIdx.y * BM;

    float acc[2][4][4];
#pragma unroll
    for (int a_ = 0; a_ < 2; a_++)
#pragma unroll
        for (int b_ = 0; b_ < 4; b_++)
#pragma unroll
            for (int c_ = 0; c_ < 4; c_++) acc[a_][b_][c_] = 0.0f;

    auto load_stage = [&](int buf, int k0) {
#pragma unroll
        for (int t = tid; t < BM * (BK/8); t += NTH) {
            int r = t >> 2, seg = t & 3;
            cp16(smem_u32(&As[buf][r][seg*8]), &A[(rowbase + r) * WDIM + k0 + seg*8]);
        }
#pragma unroll
        for (int t = tid; t < BN * (BK/8); t += NTH) {
            int r = t >> 2, seg = t & 3;
            cp16(smem_u32(&Bs[buf][r][seg*8]), &BT[(long)r * WDIM + k0 + seg*8]);
        }
        cp_commit();
    };

    constexpr int NS = WDIM / BK;
    load_stage(0, 0);
    for (int s = 0; s < NS; s++) {
        int cur = s & 1;
        if (s + 1 < NS) { load_stage(cur ^ 1, (s + 1) * BK); cp_wait1(); }
        else cp_wait0();
        __syncthreads();
#pragma unroll
        for (int kk = 0; kk < BK; kk += 16) {
            uint32_t a[2][4], b[4][2];
#pragma unroll
            for (int sm_ = 0; sm_ < 2; sm_++) {
                int r = wm*32 + sm_*16;
                a[sm_][0] = *(const uint32_t*)&As[cur][r + g    ][kk + t4*2    ];
                a[sm_][1] = *(const uint32_t*)&As[cur][r + g + 8][kk + t4*2    ];
                a[sm_][2] = *(const uint32_t*)&As[cur][r + g    ][kk + t4*2 + 8];
                a[sm_][3] = *(const uint32_t*)&As[cur][r + g + 8][kk + t4*2 + 8];
            }
#pragma unroll
            for (int j = 0; j < 4; j++) {
                int n = j*8;
                b[j][0] = *(const uint32_t*)&Bs[cur][n + g][kk + t4*2    ];
                b[j][1] = *(const uint32_t*)&Bs[cur][n + g][kk + t4*2 + 8];
            }
#pragma unroll
            for (int sm_ = 0; sm_ < 2; sm_++)
#pragma unroll
                for (int j = 0; j < 4; j++)
                    mma16816(acc[sm_][j], a[sm_], b[j]);
        }
        __syncthreads();
    }

#pragma unroll
    for (int sm_ = 0; sm_ < 2; sm_++) {
#pragma unroll
        for (int j = 0; j < 4; j++) {
            int r0 = wm*32 + sm_*16 + g;
            int c0 = j*8 + t4*2;
            if (c0 < 27) {
                cs_s[r0][c0]     = acc[sm_][j][0] + bias[c0];
                cs_s[r0 + 8][c0] = acc[sm_][j][2] + bias[c0];
            }
            if (c0 + 1 < 27) {
                cs_s[r0][c0 + 1]     = acc[sm_][j][1] + bias[c0 + 1];
                cs_s[r0 + 8][c0 + 1] = acc[sm_][j][3] + bias[c0 + 1];
            }
        }
    }
    __syncthreads();

    long i = rowbase + tid;
    float coe[9];
#pragma unroll
    for (int k = 0; k < 9; k++) coe[k] = feature[i*16 + 1 + k];
    float rr = 0.f, gg = 0.f, bb = 0.f;
#pragma unroll
    for (int k = 0; k < 9; k++) {
        rr += cs_s[tid][k]      * coe[k];
        gg += cs_s[tid][9 + k]  * coe[k];
        bb += cs_s[tid][18 + k] * coe[k];
    }
    float gate[3] = {sigmoidf_(rr), sigmoidf_(gg), sigmoidf_(bb)};
#pragma unroll
    for (int cc = 0; cc < 3; cc++) {
        float spec = sigmoidf_(feature[i*16 + 13 + cc]);
        float light = out[(size_t)12*N + 3*i + cc];
        float specular = spec * light * gate[cc];
        out[(size_t)9*N + 3*i + cc] = specular;
        out[3*i + cc] = out[(size_t)6*N + 3*i + cc] + specular;
    }
}

// ---------------- weight prep (+ consts, merged) ----------------
__global__ void prep_weights_kernel(const float* __restrict__ w1, const float* __restrict__ w2,
                                    const float* __restrict__ w3, const float* __restrict__ wc,
                                    const float* __restrict__ bc) {
    int idx = blockIdx.x * blockDim.x + threadIdx.x;
    if (idx == 0) {
        double fact[22];
        fact[0] = 1.0;
        for (int i = 1; i <= 21; i++) fact[i] = fact[i-1] * i;
        for (int l = 0; l <= LMAXX; l++)
            for (int m = 0; m <= l; m++) {
                double K = sqrt((2.0*l + 1.0) / (4.0*M_PI) * fact[l-m] / fact[l+m]);
                g_KTAB[l][m] = (float)(m == 0 ? K : sqrt(2.0) * K);
            }
        double df = 1.0;
        g_DFACT[0] = 1.0f;
        for (int m = 1; m <= LMAXX; m++) { df *= (2.0*m - 1.0); g_DFACT[m] = (float)df; }
    }
    const int NW = 3 * WDIM * WDIM;
    if (idx < NW) {
        int which = idx >> 18;
        int r = idx & (WDIM*WDIM - 1);
        int k = r >> 9, n = r & 511;
        const float* w = (which == 0) ? w1 : (which == 1) ? w2 : w3;
        __half* o = (which == 0) ? g_w1T : (which == 1) ? g_w2T : g_w3T;
        o[n*WDIM + k] = __float2half(w[k*WDIM + n]);
    } else if (idx < NW + 32*WDIM) {
        int r = idx - NW;
        int k = r & 511, n = r >> 9;
        g_wcT[n*WDIM + k] = __float2half(n < 27 ? wc[k*27 + n] : 0.0f);
    } else if (idx < NW + 32*WDIM + 32) {
        int n = idx - (NW + 32*WDIM);
        g_bcPad[n] = n < 27 ? bc[n] : 0.0f;
    }
}

// ---------------- physics v2: 128 threads/CTA, 4 threads per point (m mod 4 split) ----------------
__global__ void __launch_bounds__(128) physics_kernel_v2(
    const float* __restrict__ normals,
    const float* __restrict__ viewd,
    const float* __restrict__ feature,
    const float* __restrict__ refSH,
    float* __restrict__ out, int N) {
    __shared__ float ss[32 * 363];       // 46464 B
    __shared__ float sWl[32][11];        // 1408 B
    int tid = threadIdx.x;
    int base = blockIdx.x * 32;
    int p = tid >> 2;                    // point within CTA (0..31)
    int sub = tid & 3;                   // m-phase (0..3)
    int i = base + p;

    // cooperative staging: 2904 float4 over 128 threads
    {
        const float4* src = (const float4*)(refSH + (size_t)base * 363);
        float4* dst = (float4*)ss;
        for (int t = tid; t < (32 * 363) / 4; t += 128) dst[t] = src[t];
    }

    float nx = normals[i*3+0], ny = normals[i*3+1], nz = normals[i*3+2];
    float vx = viewd[i*3+0],   vy = viewd[i*3+1],   vz = viewd[i*3+2];
    float f0 = feature[i*16];
    float rough = fmaxf(f0, 0.0f) + log1pf(expf(-fabsf(f0)));
    float dotnv = nx*vx + ny*vy + nz*vz;
    float wx = 2.0f*nx*dotnv - vx;
    float wy = 2.0f*ny*dotnv - vy;
    float wz = 2.0f*nz*dotnv - vz;

    // decay weights: thread sub computes l = sub, sub+4, sub+8
    for (int l = sub; l <= LMAXX; l += 4)
        sWl[p][l] = expf(-(float)(l*(l+1)) * 0.5f * rough);
    __syncthreads();

    const float* row = ss + p * 363;

    // (x+iy)^m stepping: start at m=sub, step by 4
    float pAc = 1.0f, pAs = 0.0f, pBc = 1.0f, pBs = 0.0f;
    for (int t = 0; t < sub; t++) {
        float na = nx*pAc - ny*pAs; pAs = nx*pAs + ny*pAc; pAc = na;
        float nb = wx*pBc - wy*pBs; pBs = wx*pBs + wy*pBc; pBc = nb;
    }
    float a2c = nx*nx - ny*ny, a2s = 2.0f*nx*ny;
    float p4Ac = a2c*a2c - a2s*a2s, p4As = 2.0f*a2c*a2s;
    float b2c = wx*wx - wy*wy, b2s = 2.0f*wx*wy;
    float p4Bc = b2c*b2c - b2s*b2s, p4Bs = 2.0f*b2c*b2s;

    float aI[3] = {0.f,0.f,0.f}, aL[3] = {0.f,0.f,0.f};

    for (int m = sub; m <= LMAXX; m += 4) {
        float cAm = pAc, sAm = pAs, cBm = pBc, sBm = pBs;
        float QAa = g_DFACT[m], QBa = QAa;
        // l = m
        {
            float kw = g_KTAB[m][m];
            float fA = kw * QAa * LAMBERT_C[m];
            float fB = kw * QBa * sWl[p][m];
            int b = (m*m + m) * 3;
            if (m == 0) {
#pragma unroll
                for (int cc = 0; cc < 3; cc++) {
                    float rv = row[b+cc];
                    aI[cc] += fA*rv; aL[cc] += fB*rv;
                }
            } else {
                float pA_ = fA*cAm, qA_ = fA*sAm;
                float pB_ = fB*cBm, qB_ = fB*sBm;
#pragma unroll
                for (int cc = 0; cc < 3; cc++) {
                    float rp_ = row[b+3*m+cc], rm_ = row[b-3*m+cc];
                    aI[cc] += pA_*rp_ + qA_*rm_;
                    aL[cc] += pB_*rp_ + qB_*rm_;
                }
            }
        }
        if (m < LMAXX) {
            float QAb = (2.0f*m + 1.0f) * nz * QAa;
            float QBb = (2.0f*m + 1.0f) * wz * QBa;
            {
                int l = m + 1;
                float kw = g_KTAB[l][m];
                float fA = kw * QAb * LAMBERT_C[l];
                float fB = kw * QBb * sWl[p][l];
                int b = (l*l + l) * 3;
                if (m == 0) {
#pragma unroll
                    for (int cc = 0; cc < 3; cc++) {
                        float rv = row[b+cc];
                        aI[cc] += fA*rv; aL[cc] += fB*rv;
                    }
                } else {
                    float pA_ = fA*cAm, qA_ = fA*sAm;
                    float pB_ = fB*cBm, qB_ = fB*sBm;
#pragma unroll
                    for (int cc = 0; cc < 3; cc++) {
                        float rp_ = row[b+3*m+cc], rm_ = row[b-3*m+cc];
                        aI[cc] += pA_*rp_ + qA_*rm_;
                        aL[cc] += pB_*rp_ + qB_*rm_;
                    }
                }
            }
            for (int l = m + 2; l <= LMAXX; l++) {
                float inv_lm = 1.0f / (float)(l - m);
                float c1 = (2.0f*l - 1.0f), c2 = (float)(l + m - 1);
                float QAc = (c1 * nz * QAb - c2 * QAa) * inv_lm;
                float QBc = (c1 * wz * QBb - c2 * QBa) * inv_lm;
                QAa = QAb; QAb = QAc;
                QBa = QBb; QBb = QBc;
                float kw = g_KTAB[l][m];
                float fA = kw * QAc * LAMBERT_C[l];
                float fB = kw * QBc * sWl[p][l];
                int b = (l*l + l) * 3;
                if (m == 0) {
#pragma unroll
                    for (int cc = 0; cc < 3; cc++) {
                        float rv = row[b+cc];
                        aI[cc] += fA*rv; aL[cc] += fB*rv;
                    }
                } else {
                    float pA_ = fA*cAm, qA_ = fA*sAm;
                    float pB_ = fB*cBm, qB_ = fB*sBm;
#pragma unroll
                    for (int cc = 0; cc < 3; cc++) {
                        float rp_ = row[b+3*m+cc], rm_ = row[b-3*m+cc];
                        aI[cc] += pA_*rp_ + qA_*rm_;
                        aL[cc] += pB_*rp_ + qB_*rm_;
                    }
                }
            }
        }
        // advance (x+iy)^m by ^4
        float na = pAc*p4Ac - pAs*p4As; pAs = pAc*p4As + pAs*p4Ac; pAc = na;
        float nb = pBc*p4Bc - pBs*p4Bs; pBs = pBc*p4Bs + pBs*p4Bc; pBc = nb;
    }

    // reduce across the 4-lane group
#pragma unroll
    for (int off = 1; off < 4; off <<= 1) {
#pragma unroll
        for (int cc = 0; cc < 3; cc++) {
            aI[cc] += __shfl_xor_sync(0xffffffffu, aI[cc], off);
            aL[cc] += __shfl_xor_sync(0xffffffffu, aL[cc], off);
        }
    }

    if (sub == 0) {
#pragma unroll
        for (int cc = 0; cc < 3; cc++) {
            float ir = fmaxf(aI[cc], 0.0f);
            float li = fmaxf(aL[cc], 0.0f);
            float alb = sigmoidf_(feature[i*16 + 10 + cc]);
            out[(size_t)3*N  + 3*i + cc] = alb;
            out[(size_t)6*N  + 3*i + cc] = alb * ir;
            out[(size_t)12*N + 3*i + cc] = li;
            out[(size_t)15*N + 3*i + cc] = ir;
        }
        float* h = g_h0 + (size_t)i * 8;
        h[0] = dotnv; h[1] = vx; h[2] = vy; h[3] = vz;
        h[4] = nx; h[5] = ny; h[6] = nz; h[7] = rough;
    }
}

// ---------------- layer0 v3 ----------------
__global__ void __launch_bounds__(256) layer0_kernel_v3(
    const float* __restrict__ w0, const float* __restrict__ b0, int N) {
    __shared__ float sw[8 * WDIM];
    __shared__ float sbias[WDIM];
    __shared__ float sh[64 * 8];
    int tid = threadIdx.x;
    long base = (long)blockIdx.x * 64;

    for (int i = tid; i < 8 * WDIM; i += 256) sw[i] = w0[i];
    for (int i = tid; i < WDIM; i += 256) sbias[i] = b0[i];
    for (int i = tid; i < 64 * 8 / 4; i += 256)
        ((float4*)sh)[i] = ((const float4*)(g_h0 + base * 8))[i];
    __syncthreads();

    int c0 = (tid & 127) * 4;
    int rg = tid >> 7;

    float w[8][4], bb[4];
#pragma unroll
    for (int j = 0; j < 8; j++)
#pragma unroll
        for (int i = 0; i < 4; i++) w[j][i] = sw[j * WDIM + c0 + i];
#pragma unroll
    for (int i = 0; i < 4; i++) bb[i] = sbias[c0 + i];

    for (int r = rg; r < 64; r += 2) {
        const float* hh = sh + r * 8;
        __half res[4];
#pragma unroll
        for (int i = 0; i < 4; i++) {
            float acc = bb[i];
#pragma unroll
            for (int j = 0; j < 8; j++) acc += hh[j] * w[j][i];
            res[i] = __float2half(fmaxf(acc, 0.0f));
        }
        *(uint2*)&g_act0[(base + r) * WDIM + c0] = *(uint2*)res;
    }
}

// ---------------- launch ----------------
extern "C" void kernel_launch(void* const* d_in, const int* in_sizes, int n_in,
                              void* d_out, int out_size) {
    const float* normals = (const float*)d_in[0];
    const float* viewd   = (const float*)d_in[1];
    const float* feature = (const float*)d_in[2];
    const float* refSH   = (const float*)d_in[3];
    const float* w0 = (const float*)d_in[4];
    const float* b0 = (const float*)d_in[5];
    const float* b1 = (const float*)d_in[7];
    const float* b2 = (const float*)d_in[9];
    const float* b3 = (const float*)d_in[11];
    int N = in_sizes[0] / 3;
    float* out = (float*)d_out;

    __half *act0, *act1, *w1T, *w2T, *w3T, *wcT;
    float *bcPad;
    cudaGetSymbolAddress((void**)&act0, g_act0);
    cudaGetSymbolAddress((void**)&act1, g_act1);
    cudaGetSymbolAddress((void**)&w1T, g_w1T);
    cudaGetSymbolAddress((void**)&w2T, g_w2T);
    cudaGetSymbolAddress((void**)&w3T, g_w3T);
    cudaGetSymbolAddress((void**)&wcT, g_wcT);
    cudaGetSymbolAddress((void**)&bcPad, g_bcPad);

    cudaFuncSetAttribute(gemm_uni_kernel, cudaFuncAttributeMaxDynamicSharedMemorySize, G_SMEM);
    cudaFuncSetAttribute(gemm_uni_kernel, cudaFuncAttributePreferredSharedMemoryCarveout,
                         cudaSharedmemCarveoutMaxShared);

    int prepTotal = 3*WDIM*WDIM + 32*WDIM + 32;
    prep_weights_kernel<<<(prepTotal + 255)/256, 256>>>((const float*)d_in[6], (const float*)d_in[8],
                                                        (const float*)d_in[10], (const float*)d_in[12],
                                                        (const float*)d_in[13]);

    physics_kernel_v2<<<N/32, 128>>>(normals, viewd, feature, refSH, out, N);

    layer0_kernel_v3<<<N/64, 256>>>(w0, b0, N);

    dim3 gg(WDIM/128, N/128);   // 4 x 1024
    gemm_uni_kernel<<<gg, 256, G_SMEM>>>(act0, w1T, b1, act1, N);
    gemm_uni_kernel<<<gg, 256, G_SMEM>>>(act1, w2T, b2, act0, N);
    gemm_uni_kernel<<<gg, 256, G_SMEM>>>(act0, w3T, b3, act1, N);

    wc_final_kernel<<<dim3(1, N/128), 128>>>(act1, wcT, bcPad, feature, out, N);
}